// round 1
// baseline (speedup 1.0000x reference)
#include <cuda_runtime.h>
#include <cstdint>

// Problem constants (fixed shapes for this registry entry)
#define D4 64          // 256 floats = 64 float4 per row
#define NUM_GRAPHS 8192

// Per-graph scratch: cond_pool [B, 256] f32 (gated mean, 0 if gate false)
__device__ float4 g_cond_pool[NUM_GRAPHS * D4];

// ---------------------------------------------------------------------------
// Kernel 1: one CTA (64 threads) per graph.
// batch is sorted, so graph g owns a contiguous node range found by binary
// search. Accumulate sum of rows with label == -1, count them, compute gate
// from the last node's label, write the gated mean into g_cond_pool.
// ---------------------------------------------------------------------------
__global__ __launch_bounds__(64)
void pool_kernel(const float4* __restrict__ node4,
                 const int*    __restrict__ batch,
                 const int*    __restrict__ label,
                 int n)
{
    const int g   = blockIdx.x;
    const int tid = threadIdx.x;   // 0..63, owns dims [tid*4, tid*4+4)

    __shared__ int s_range[2];     // start, end

    // threads 0/1 binary-search lower_bound(batch, g) / lower_bound(batch, g+1)
    if (tid < 2) {
        int key = g + tid;         // tid==0 -> g, tid==1 -> g+1
        int lo = 0, hi = n;
        while (lo < hi) {
            int mid = (lo + hi) >> 1;
            if (batch[mid] < key) lo = mid + 1;
            else                  hi = mid;
        }
        s_range[tid] = lo;
    }
    __syncthreads();
    const int start = s_range[0];
    const int end   = s_range[1];

    float4 acc = make_float4(0.f, 0.f, 0.f, 0.f);
    float  cnt = 0.f;

    for (int i = start; i < end; ++i) {
        if (label[i] == -1) {                     // broadcast L1 hit across CTA
            float4 v = node4[(size_t)i * D4 + tid];
            acc.x += v.x; acc.y += v.y; acc.z += v.z; acc.w += v.w;
            cnt += 1.f;
        }
    }

    bool gate = (end > start) && (label[end - 1] == -1);
    float inv = gate ? (1.f / fmaxf(cnt, 1.f)) : 0.f;

    float4 r = make_float4(acc.x * inv, acc.y * inv, acc.z * inv, acc.w * inv);
    g_cond_pool[(size_t)g * D4 + tid] = r;
}

// ---------------------------------------------------------------------------
// Kernel 2: streaming assembly. Output row = [node_rep[i] (256f) | pool (256f)].
// One thread per float4 of output. 128 float4 per row; each 32-thread warp is
// entirely inside one row and one half -> warp-uniform branch, coalesced I/O.
// ---------------------------------------------------------------------------
__global__ __launch_bounds__(256)
void assemble_kernel(const float4* __restrict__ node4,
                     const int*    __restrict__ batch,
                     float4*       __restrict__ out4,
                     int n)
{
    const long long idx   = (long long)blockIdx.x * blockDim.x + threadIdx.x;
    const long long total = (long long)n * 128;
    if (idx >= total) return;

    const int row = (int)(idx >> 7);
    const int c   = (int)(idx & 127);

    float4 v;
    if (c < D4) {
        v = node4[(size_t)row * D4 + c];
    } else {
        int g = batch[row];                       // one broadcast load per warp
        v = g_cond_pool[(size_t)g * D4 + (c - D4)];
    }
    out4[idx] = v;
}

// ---------------------------------------------------------------------------
// Launch: inputs are [node_rep f32 NxD, batch i32 N, primary_label i32 N,
//                     num_graphs i32 (scalar)]. Output f32 Nx2D.
// ---------------------------------------------------------------------------
extern "C" void kernel_launch(void* const* d_in, const int* in_sizes, int n_in,
                              void* d_out, int out_size)
{
    const float4* node4 = (const float4*)d_in[0];
    const int*    batch = (const int*)d_in[1];
    const int*    label = (const int*)d_in[2];
    const int     n     = in_sizes[1];           // node count

    pool_kernel<<<NUM_GRAPHS, 64>>>(node4, batch, label, n);

    const long long total  = (long long)n * 128; // output float4 count
    const int       tpb    = 256;
    const int       blocks = (int)((total + tpb - 1) / tpb);
    assemble_kernel<<<blocks, tpb>>>(node4, batch, (float4*)d_out, n);
}

// round 3
// speedup vs baseline: 1.2619x; 1.2619x over previous
#include <cuda_runtime.h>
#include <cstdint>

// Fixed shapes for this registry entry
#define D4   64        // 256 floats = 64 float4 per row (input)
#define OD4  128       // 512 floats = 128 float4 per row (output)
#define TPB  128

// ---------------------------------------------------------------------------
// Fused kernel: one CTA (128 threads) per graph.
// Phase 1: binary-search the graph's contiguous node range (batch is sorted).
// Phase 2: accumulate masked (label==-1) column sums; thread t owns the
//          float2 at dim offset 2t. Gate on last node's label; scale.
// Phase 3: stream output rows for this range. Threads 0..63 copy node_rep
//          (float4, coalesced); threads 64..127 write the pool vector held
//          in a register (loaded once from smem). Warp-uniform split.
// ---------------------------------------------------------------------------
__global__ __launch_bounds__(TPB)
void fused_kernel(const float4* __restrict__ node4,
                  const int*    __restrict__ batch,
                  const int*    __restrict__ label,
                  float4*       __restrict__ out4,
                  int n)
{
    const int g   = blockIdx.x;
    const int tid = threadIdx.x;

    __shared__ int s_range[2];
    __shared__ __align__(16) float4 s_pool[64];    // 256 floats, 16B-aligned

    if (tid < 2) {                     // lower_bound(batch, g) / (g+1)
        int key = g + tid;
        int lo = 0, hi = n;
        while (lo < hi) {
            int mid = (lo + hi) >> 1;
            if (batch[mid] < key) lo = mid + 1;
            else                  hi = mid;
        }
        s_range[tid] = lo;
    }
    __syncthreads();
    const int start = s_range[0];
    const int end   = s_range[1];

    // ---- Phase 2: masked column-sum; each thread owns dims [2t, 2t+2) ----
    const float2* node2 = (const float2*)node4;
    float2 acc = make_float2(0.f, 0.f);
    float  cnt = 0.f;
    for (int i = start; i < end; ++i) {
        if (label[i] == -1) {                          // broadcast, L1-hot
            float2 v = node2[(size_t)i * 128 + tid];   // coalesced 1KB/row
            acc.x += v.x; acc.y += v.y; cnt += 1.f;
        }
    }
    bool  gate = (end > start) && (label[end - 1] == -1);
    float inv  = gate ? (1.f / fmaxf(cnt, 1.f)) : 0.f;
    ((float2*)s_pool)[tid] = make_float2(acc.x * inv, acc.y * inv);
    __syncthreads();

    // Preload this thread's assembly value source (aligned LDS.128)
    float4 poolv = make_float4(0.f, 0.f, 0.f, 0.f);
    if (tid >= 64) poolv = s_pool[tid - 64];

    // ---- Phase 3: stream output rows [node_rep | pool] ----
    #pragma unroll 4
    for (int i = start; i < end; ++i) {
        float4 v;
        if (tid < 64) v = node4[(size_t)i * D4 + tid]; // L1/L2 hit for cond rows
        else          v = poolv;
        out4[(size_t)i * OD4 + tid] = v;               // coalesced 2KB/row
    }
}

// ---------------------------------------------------------------------------
// Inputs: [node_rep f32 N*256, batch i32 N, primary_label i32 N, num_graphs]
// Output: f32 N*512. Grid = num_graphs (8192) CTAs; every node row is owned
// by exactly one graph, so all output rows are written.
// ---------------------------------------------------------------------------
extern "C" void kernel_launch(void* const* d_in, const int* in_sizes, int n_in,
                              void* d_out, int out_size)
{
    const float4* node4 = (const float4*)d_in[0];
    const int*    batch = (const int*)d_in[1];
    const int*    label = (const int*)d_in[2];
    const int     n     = in_sizes[1];
    const int     B     = 8192;

    fused_kernel<<<B, TPB>>>(node4, batch, label, (float4*)d_out, n);
}

// round 4
// speedup vs baseline: 1.3486x; 1.0687x over previous
#include <cuda_runtime.h>
#include <cstdint>

#define D4   64        // 256 floats = 64 float4 per input row
#define OD4  128       // 512 floats = 128 float4 per output row
#define TPB  128

// ---------------------------------------------------------------------------
// Fused kernel: one CTA (128 threads) per graph (batch sorted).
// Phase 1: binary-search the graph's node range.
// Phase 2: ONLY if gate (label[end-1] == -1): masked column mean.
//          Gate-false graphs (~80%) skip the scan — pool is exactly 0.
// Phase 3: stream 2 output rows per iteration. All 128 threads load
//          contiguous node_rep (rows i, i+1), each stores its node float4
//          and its pool float4. Streaming stores (__stcs).
// ---------------------------------------------------------------------------
__global__ __launch_bounds__(TPB, 16)
void fused_kernel(const float4* __restrict__ node4,
                  const int*    __restrict__ batch,
                  const int*    __restrict__ label,
                  float4*       __restrict__ out4,
                  int n)
{
    const int g   = blockIdx.x;
    const int tid = threadIdx.x;

    __shared__ int s_range[2];
    __shared__ __align__(16) float4 s_pool[64];    // 256 floats

    if (tid < 2) {                                 // lower_bound(batch, g)/(g+1)
        int key = g + tid;
        int lo = 0, hi = n;
        while (lo < hi) {
            int mid = (lo + hi) >> 1;
            if (batch[mid] < key) lo = mid + 1;
            else                  hi = mid;
        }
        s_range[tid] = lo;
    }
    __syncthreads();
    const int start = s_range[0];
    const int end   = s_range[1];

    // ---- Gate first: pool is identically 0 unless last node's label == -1 ----
    const bool gate = (end > start) && (label[end - 1] == -1);

    if (gate) {
        // masked column-sum; thread t owns dims [2t, 2t+2)
        const float2* node2 = (const float2*)node4;
        float2 acc = make_float2(0.f, 0.f);
        float  cnt = 0.f;
        for (int i = start; i < end; ++i) {
            if (label[i] == -1) {                      // broadcast load
                float2 v = node2[(size_t)i * 128 + tid];
                acc.x += v.x; acc.y += v.y; cnt += 1.f;
            }
        }
        float inv = 1.f / fmaxf(cnt, 1.f);
        ((float2*)s_pool)[tid] = make_float2(acc.x * inv, acc.y * inv);
    } else {
        ((float2*)s_pool)[tid] = make_float2(0.f, 0.f);
    }
    __syncthreads();

    const int    c     = tid & 63;         // column (float4) within half-row
    const int    half  = tid >> 6;         // 0: row i, 1: row i+1
    const float4 poolv = s_pool[c];

    // ---- Phase 3: 2 rows per iteration; contiguous 2KB load per CTA ----
    int i = start;
    #pragma unroll 2
    for (; i + 2 <= end; i += 2) {
        float4 v = node4[(size_t)i * D4 + tid];        // rows i..i+1, contiguous
        size_t rbase = (size_t)(i + half) * OD4;
        __stcs(&out4[rbase + c],      v);
        __stcs(&out4[rbase + 64 + c], poolv);
    }
    if (i < end) {                                     // odd remainder row
        size_t rbase = (size_t)i * OD4;
        if (half == 0) {
            float4 v = node4[(size_t)i * D4 + c];
            __stcs(&out4[rbase + c], v);
        } else {
            __stcs(&out4[rbase + 64 + c], poolv);
        }
    }
}

// ---------------------------------------------------------------------------
// Inputs: [node_rep f32 N*256, batch i32 N, primary_label i32 N, num_graphs]
// Output: f32 N*512.
// ---------------------------------------------------------------------------
extern "C" void kernel_launch(void* const* d_in, const int* in_sizes, int n_in,
                              void* d_out, int out_size)
{
    const float4* node4 = (const float4*)d_in[0];
    const int*    batch = (const int*)d_in[1];
    const int*    label = (const int*)d_in[2];
    const int     n     = in_sizes[1];
    const int     B     = 8192;

    fused_kernel<<<B, TPB>>>(node4, batch, label, (float4*)d_out, n);
}

// round 5
// speedup vs baseline: 1.4010x; 1.0389x over previous
#include <cuda_runtime.h>
#include <cstdint>

#define D4   64        // 256 floats = 64 float4 per input row
#define OD4  128       // 512 floats = 128 float4 per output row
#define TPB  128
#define NUM_GRAPHS 8192

// Graph boundaries: bound[g] = first row index with batch[i] >= g; bound[B] = n
__device__ int g_bound[NUM_GRAPHS + 1];

// ---------------------------------------------------------------------------
// Kernel 1: boundary extraction from sorted batch. O(N), fully parallel.
// ---------------------------------------------------------------------------
__global__ __launch_bounds__(256)
void bounds_kernel(const int* __restrict__ batch, int n)
{
    int i = blockIdx.x * blockDim.x + threadIdx.x;
    if (i >= n) return;
    int b1 = batch[i];
    int b0 = (i == 0) ? -1 : batch[i - 1];
    for (int g = b0 + 1; g <= b1; ++g) g_bound[g] = i;     // covers empty graphs
    if (i == n - 1)
        for (int g = b1 + 1; g <= NUM_GRAPHS; ++g) g_bound[g] = n;
}

// ---------------------------------------------------------------------------
// Kernel 2: fused pool + assemble. One CTA (128 threads) per graph.
// Gate-false graphs (~80%) skip smem/sync entirely (pool == 0).
// Stream loop: 4 rows/iter, 2 independent LDG.128 + 4 STG.128 per thread.
// ---------------------------------------------------------------------------
__global__ __launch_bounds__(TPB, 16)
void fused_kernel(const float4* __restrict__ node4,
                  const int*    __restrict__ label,
                  float4*       __restrict__ out4)
{
    const int g   = blockIdx.x;
    const int tid = threadIdx.x;

    const int start = g_bound[g];         // L2/L1-hot broadcast loads
    const int end   = g_bound[g + 1];
    if (start >= end) return;

    __shared__ __align__(16) float4 s_pool[64];

    const bool gate = (label[end - 1] == -1);

    float4 poolv = make_float4(0.f, 0.f, 0.f, 0.f);
    if (gate) {                            // CTA-uniform branch
        // masked column-sum; thread t owns dims [2t, 2t+2)
        const float2* node2 = (const float2*)node4;
        float2 acc = make_float2(0.f, 0.f);
        float  cnt = 0.f;
        for (int i = start; i < end; ++i) {
            if (label[i] == -1) {
                float2 v = node2[(size_t)i * 128 + tid];
                acc.x += v.x; acc.y += v.y; cnt += 1.f;
            }
        }
        float inv = 1.f / fmaxf(cnt, 1.f);
        ((float2*)s_pool)[tid] = make_float2(acc.x * inv, acc.y * inv);
        __syncthreads();
        poolv = s_pool[tid & 63];
    }

    const int c = tid & 63;               // column (float4) within half-row
    const int r = tid >> 6;               // row parity within the 2-row tile

    // ---- stream 4 rows per iteration ----
    int i = start;
    for (; i + 4 <= end; i += 4) {
        float4 v0 = node4[(size_t)i * D4 + tid];          // rows i,   i+1
        float4 v1 = node4[(size_t)(i + 2) * D4 + tid];    // rows i+2, i+3
        size_t rb0 = (size_t)(i + r)     * OD4;
        size_t rb1 = (size_t)(i + 2 + r) * OD4;
        __stcs(&out4[rb0 + c],      v0);
        __stcs(&out4[rb0 + 64 + c], poolv);
        __stcs(&out4[rb1 + c],      v1);
        __stcs(&out4[rb1 + 64 + c], poolv);
    }
    for (; i + 2 <= end; i += 2) {                        // 2-row tail
        float4 v = node4[(size_t)i * D4 + tid];
        size_t rb = (size_t)(i + r) * OD4;
        __stcs(&out4[rb + c],      v);
        __stcs(&out4[rb + 64 + c], poolv);
    }
    if (i < end) {                                        // odd remainder row
        size_t rb = (size_t)i * OD4;
        if (r == 0) {
            float4 v = node4[(size_t)i * D4 + c];
            __stcs(&out4[rb + c], v);
        } else {
            __stcs(&out4[rb + 64 + c], poolv);
        }
    }
}

// ---------------------------------------------------------------------------
// Inputs: [node_rep f32 N*256, batch i32 N, primary_label i32 N, num_graphs]
// Output: f32 N*512.
// ---------------------------------------------------------------------------
extern "C" void kernel_launch(void* const* d_in, const int* in_sizes, int n_in,
                              void* d_out, int out_size)
{
    const float4* node4 = (const float4*)d_in[0];
    const int*    batch = (const int*)d_in[1];
    const int*    label = (const int*)d_in[2];
    const int     n     = in_sizes[1];

    bounds_kernel<<<(n + 255) / 256, 256>>>(batch, n);
    fused_kernel<<<NUM_GRAPHS, TPB>>>(node4, label, (float4*)d_out);
}

// round 6
// speedup vs baseline: 1.4462x; 1.0322x over previous
#include <cuda_runtime.h>
#include <cstdint>

#define D4   64        // 256 floats = 64 float4 per input row
#define OD4  128       // 512 floats = 128 float4 per output row
#define TPB  128
#define NUM_GRAPHS 8192

// Graph boundaries: bound[g] = first row index with batch[i] >= g; bound[B] = n
__device__ int g_bound[NUM_GRAPHS + 1];

// ---------------------------------------------------------------------------
// Kernel 1: boundary extraction from sorted batch. int4-vectorized, 4/thread.
// For each position i with batch[i-1] < batch[i], fill bound[batch[i-1]+1 ..
// batch[i]] = i. Thread handling i=0 also fills the low end; the thread
// owning the last element fills the high end.
// ---------------------------------------------------------------------------
__global__ __launch_bounds__(256)
void bounds_kernel(const int* __restrict__ batch, int n)
{
    int t = blockIdx.x * blockDim.x + threadIdx.x;
    int i0 = t * 4;
    if (i0 >= n) return;

    int b[5];                         // batch[i0-1 .. i0+3] (clamped)
    b[0] = (i0 == 0) ? -1 : batch[i0 - 1];
    if (i0 + 4 <= n && (i0 & 3) == 0) {
        int4 v = *(const int4*)(batch + i0);
        b[1] = v.x; b[2] = v.y; b[3] = v.z; b[4] = v.w;
    } else {
        #pragma unroll
        for (int k = 0; k < 4; ++k)
            b[k + 1] = (i0 + k < n) ? batch[i0 + k] : -2;
    }

    #pragma unroll
    for (int k = 0; k < 4; ++k) {
        int i = i0 + k;
        if (i >= n) break;
        for (int g = b[k] + 1; g <= b[k + 1]; ++g) g_bound[g] = i;
        if (i == n - 1)
            for (int g = b[k + 1] + 1; g <= NUM_GRAPHS; ++g) g_bound[g] = n;
    }
}

// ---------------------------------------------------------------------------
// Kernel 2: fused pool + assemble. One CTA (128 threads) per graph.
// Gate-false graphs (~80%) skip smem/sync entirely (pool == 0).
// Stream loop: 8 rows/iter -> 4 independent LDG.128 per thread (__ldcs),
// 8 STG.128 (__stcs). 2KB-contiguous loads, 16KB-contiguous stores per CTA.
// ---------------------------------------------------------------------------
__global__ __launch_bounds__(TPB, 16)
void fused_kernel(const float4* __restrict__ node4,
                  const int*    __restrict__ label,
                  float4*       __restrict__ out4)
{
    const int g   = blockIdx.x;
    const int tid = threadIdx.x;

    const int start = g_bound[g];         // L2-hot broadcast loads
    const int end   = g_bound[g + 1];
    if (start >= end) return;

    __shared__ __align__(16) float4 s_pool[64];

    const bool gate = (label[end - 1] == -1);

    float4 poolv = make_float4(0.f, 0.f, 0.f, 0.f);
    if (gate) {                            // CTA-uniform branch
        const float2* node2 = (const float2*)node4;
        float2 acc = make_float2(0.f, 0.f);
        float  cnt = 0.f;
        for (int i = start; i < end; ++i) {
            if (label[i] == -1) {
                float2 v = node2[(size_t)i * 128 + tid];
                acc.x += v.x; acc.y += v.y; cnt += 1.f;
            }
        }
        float inv = 1.f / fmaxf(cnt, 1.f);
        ((float2*)s_pool)[tid] = make_float2(acc.x * inv, acc.y * inv);
        __syncthreads();
        poolv = s_pool[tid & 63];
    }

    const int c = tid & 63;               // column (float4) within half-row
    const int r = tid >> 6;               // row parity within each 2-row tile

    int i = start;
    for (; i + 8 <= end; i += 8) {        // 8 rows per iteration
        float4 v0 = __ldcs(&node4[(size_t)(i    ) * D4 + tid]);
        float4 v1 = __ldcs(&node4[(size_t)(i + 2) * D4 + tid]);
        float4 v2 = __ldcs(&node4[(size_t)(i + 4) * D4 + tid]);
        float4 v3 = __ldcs(&node4[(size_t)(i + 6) * D4 + tid]);
        size_t rb0 = (size_t)(i     + r) * OD4;
        size_t rb1 = (size_t)(i + 2 + r) * OD4;
        size_t rb2 = (size_t)(i + 4 + r) * OD4;
        size_t rb3 = (size_t)(i + 6 + r) * OD4;
        __stcs(&out4[rb0 + c], v0);  __stcs(&out4[rb0 + 64 + c], poolv);
        __stcs(&out4[rb1 + c], v1);  __stcs(&out4[rb1 + 64 + c], poolv);
        __stcs(&out4[rb2 + c], v2);  __stcs(&out4[rb2 + 64 + c], poolv);
        __stcs(&out4[rb3 + c], v3);  __stcs(&out4[rb3 + 64 + c], poolv);
    }
    for (; i + 2 <= end; i += 2) {        // 2-row tail
        float4 v = __ldcs(&node4[(size_t)i * D4 + tid]);
        size_t rb = (size_t)(i + r) * OD4;
        __stcs(&out4[rb + c], v);
        __stcs(&out4[rb + 64 + c], poolv);
    }
    if (i < end) {                        // odd remainder row
        size_t rb = (size_t)i * OD4;
        if (r == 0) {
            float4 v = __ldcs(&node4[(size_t)i * D4 + c]);
            __stcs(&out4[rb + c], v);
        } else {
            __stcs(&out4[rb + 64 + c], poolv);
        }
    }
}

// ---------------------------------------------------------------------------
// Inputs: [node_rep f32 N*256, batch i32 N, primary_label i32 N, num_graphs]
// Output: f32 N*512.
// ---------------------------------------------------------------------------
extern "C" void kernel_launch(void* const* d_in, const int* in_sizes, int n_in,
                              void* d_out, int out_size)
{
    const float4* node4 = (const float4*)d_in[0];
    const int*    batch = (const int*)d_in[1];
    const int*    label = (const int*)d_in[2];
    const int     n     = in_sizes[1];

    int bthreads = (n + 3) / 4;
    bounds_kernel<<<(bthreads + 255) / 256, 256>>>(batch, n);
    fused_kernel<<<NUM_GRAPHS, TPB>>>(node4, label, (float4*)d_out);
}